// round 4
// baseline (speedup 1.0000x reference)
#include <cuda_runtime.h>
#include <cuda_bf16.h>
#include <float.h>
#include <math.h>

#define BV 128
#define BT 64
#define EMB 512
#define NP 196
#define NR 197
#define NKEEP 118
#define NNON 78
#define KP 58
#define HID 102
#define MAXKT 100
#define TOK 60

typedef unsigned long long ull;

// ---------------- device scratch ----------------
__device__ float g_inv[BV * NR];
__device__ float g_self[BV * NP];
__device__ float g_logits[BV * NP * KP];
__device__ float g_capglo[BT * EMB];
__device__ float g_selcap[BT * 30 * EMB];
__device__ int   g_nt[BT];
__device__ float g_score[BT * BV * NP];

__device__ __forceinline__ float gelu_f(float x) {
    return 0.5f * x * (1.0f + erff(x * 0.70710678118654752440f));
}

__device__ __forceinline__ ull pk2(float lo, float hi) {
    ull r; asm("mov.b64 %0,{%1,%2};" : "=l"(r) : "f"(lo), "f"(hi)); return r;
}
__device__ __forceinline__ void fma2(ull& a, ull x, ull w) {
    asm("fma.rn.f32x2 %0,%1,%2,%0;" : "+l"(a) : "l"(x), "l"(w));
}
__device__ __forceinline__ float2 upk2(ull a) {
    float lo, hi; asm("mov.b64 {%0,%1},%2;" : "=f"(lo), "=f"(hi) : "l"(a));
    return make_float2(lo, hi);
}

// float -> order-preserving uint key
__device__ __forceinline__ unsigned f2k(float f) {
    unsigned u = __float_as_uint(f);
    return (u & 0x80000000u) ? ~u : (u | 0x80000000u);
}

// block-wide sum for 256-thread blocks
__device__ __forceinline__ float bsum(float v, float* buf) {
    for (int o = 16; o; o >>= 1) v += __shfl_down_sync(0xffffffffu, v, o);
    int w = threadIdx.x >> 5, l = threadIdx.x & 31;
    if (l == 0) buf[w] = v;
    __syncthreads();
    float r = (threadIdx.x < 8) ? buf[threadIdx.x] : 0.0f;
    if (w == 0) {
        for (int o = 4; o; o >>= 1) r += __shfl_down_sync(0xffffffffu, r, o);
        if (l == 0) buf[0] = r;
    }
    __syncthreads();
    float res = buf[0];
    __syncthreads();
    return res;
}

// ---------------- K1: per-image norms, glo, self_attn ----------------
__global__ void __launch_bounds__(256) k1_img(const float* __restrict__ img) {
    int b = blockIdx.x;
    const float* base = img + (size_t)b * NR * EMB;
    __shared__ float sm[EMB];
    __shared__ float red[32];
    int tid = threadIdx.x;
    for (int c = tid; c < EMB; c += 256) {
        float s = 0.f;
        for (int j = 1; j < NR; ++j) s += base[(size_t)j * EMB + c];
        sm[c] = s * (1.0f / NP);
    }
    __syncthreads();
    float pv = 0.f;
    for (int c = tid; c < EMB; c += 256) { float v = sm[c]; pv += v * v; }
    float nn = bsum(pv, red);
    float rn = 1.f / fmaxf(sqrtf(nn), 1e-12f);
    for (int c = tid; c < EMB; c += 256) sm[c] *= rn;
    __syncthreads();
    int wid = tid >> 5, lane = tid & 31;
    for (int j = wid; j < NR; j += 8) {
        const float* r = base + (size_t)j * EMB;
        float s2 = 0.f, sd = 0.f;
        for (int k = lane; k < EMB; k += 32) { float v = r[k]; s2 += v * v; sd += v * sm[k]; }
        for (int o = 16; o; o >>= 1) {
            s2 += __shfl_down_sync(0xffffffffu, s2, o);
            sd += __shfl_down_sync(0xffffffffu, sd, o);
        }
        if (lane == 0) {
            float inv = 1.f / fmaxf(sqrtf(s2), 1e-12f);
            g_inv[b * NR + j] = inv;
            if (j >= 1) g_self[b * NP + j - 1] = sd * inv;
        }
    }
}

// ---------------- K2: caption-independent MLP logits ----------------
__global__ void __launch_bounds__(256) k2_logits(
    const float* __restrict__ img,
    const float* __restrict__ lng, const float* __restrict__ lnb,
    const float* __restrict__ w1, const float* __restrict__ b1,
    const float* __restrict__ w2, const float* __restrict__ b2) {
    extern __shared__ float w1s[];  // 512*102
    __shared__ float ln[2][EMB];
    __shared__ float gh[2][HID];
    __shared__ float red[32];
    int tid = threadIdx.x;
    for (int v = tid; v < EMB * HID; v += 256) w1s[v] = w1[v];
    int base = blockIdx.x * 64;
    for (int rr = 0; rr < 64; rr += 2) {
        __syncthreads();
        for (int r = 0; r < 2; ++r) {
            int grow = base + rr + r;
            int b = grow / NP, j = grow - b * NP;
            const float* src = img + ((size_t)(b * NR) + 1 + j) * EMB;
            for (int c = tid; c < EMB; c += 256) ln[r][c] = src[c];
        }
        __syncthreads();
        for (int r = 0; r < 2; ++r) {
            float p = 0.f;
            for (int c = tid; c < EMB; c += 256) p += ln[r][c];
            float mu = bsum(p, red) * (1.0f / EMB);
            p = 0.f;
            for (int c = tid; c < EMB; c += 256) { float d = ln[r][c] - mu; p += d * d; }
            float var = bsum(p, red) * (1.0f / EMB);
            float rstd = rsqrtf(var + 1e-5f);
            for (int c = tid; c < EMB; c += 256)
                ln[r][c] = (ln[r][c] - mu) * rstd * lng[c] + lnb[c];
            __syncthreads();
        }
        if (tid < 2 * HID) {
            int r = tid >= HID ? 1 : 0;
            int h = tid - r * HID;
            float a = 0.f;
            for (int c = 0; c < EMB; ++c) a += ln[r][c] * w1s[c * HID + h];
            gh[r][h] = gelu_f(a + b1[h]);
        }
        __syncthreads();
        if (tid < 2 * KP) {
            int r = tid >= KP ? 1 : 0;
            int p = tid - r * KP;
            float a = b2[p];
            for (int h = 0; h < HID; ++h) a += gh[r][h] * w2[h * KP + p];
            g_logits[(size_t)(base + rr + r) * KP + p] = a;
        }
    }
}

// ---------------- K3: per-caption ----------------
__global__ void __launch_bounds__(256) k3_cap(
    const float* __restrict__ cap, const int* __restrict__ lens,
    const float* __restrict__ lng, const float* __restrict__ lnb,
    const float* __restrict__ w1, const float* __restrict__ b1,
    const float* __restrict__ casc, const float* __restrict__ fw,
    const float* __restrict__ fb) {
    extern __shared__ float w1s[];   // 512*102, later overlaid with rowsb
    __shared__ float ln[2][EMB];
    __shared__ float gh[2][HID];
    __shared__ float lg[60 * 32];
    __shared__ float red[32];
    __shared__ float pb2[256];
    __shared__ float inv2[32];
    int i = blockIdx.x, tid = threadIdx.x;
    int n = lens[i], m = n - 1;
    int kt = m >> 1;
    kt = kt < 4 ? 4 : kt;
    kt = kt > MAXKT ? MAXKT : kt;
    if (kt > 29) kt = 29;
    const float* capi = cap + (size_t)i * 60 * EMB;
    for (int c = tid; c < EMB; c += 256) {
        float s = 0.f;
        for (int r = 0; r < n; ++r) s += capi[(size_t)r * EMB + c];
        ln[0][c] = s / (float)n;
    }
    __syncthreads();
    float pv = 0.f;
    for (int c = tid; c < EMB; c += 256) pv += ln[0][c] * ln[0][c];
    float nn = bsum(pv, red);
    float rn = 1.f / fmaxf(sqrtf(nn), 1e-12f);
    for (int c = tid; c < EMB; c += 256) g_capglo[i * EMB + c] = ln[0][c] * rn;
    for (int v = tid; v < EMB * HID; v += 256) w1s[v] = w1[v];
    __syncthreads();
    float cs = casc[0];
    for (int rw = 0; rw < m; rw += 2) {
        for (int r = 0; r < 2; ++r) {
            int wi = rw + r < m ? rw + r : m - 1;
            const float* src = capi + (size_t)(1 + wi) * EMB;
            for (int c = tid; c < EMB; c += 256) ln[r][c] = src[c];
        }
        __syncthreads();
        for (int r = 0; r < 2; ++r) {
            float p = 0.f;
            for (int c = tid; c < EMB; c += 256) p += ln[r][c];
            float mu = bsum(p, red) * (1.0f / EMB);
            p = 0.f;
            for (int c = tid; c < EMB; c += 256) { float d = ln[r][c] - mu; p += d * d; }
            float var = bsum(p, red) * (1.0f / EMB);
            float rstd = rsqrtf(var + 1e-5f);
            for (int c = tid; c < EMB; c += 256)
                ln[r][c] = (ln[r][c] - mu) * rstd * lng[c] + lnb[c];
            __syncthreads();
        }
        if (tid < 2 * HID) {
            int r = tid >= HID ? 1 : 0;
            int h = tid - r * HID;
            float a = 0.f;
            for (int c = 0; c < EMB; ++c) a += ln[r][c] * w1s[c * HID + h];
            gh[r][h] = gelu_f(a + b1[h]);
        }
        __syncthreads();
        if (tid < 64) {
            int r = tid >> 5, t = tid & 31;
            int rowg = rw + r;
            if (t < kt && rowg < m) {
                float a = fb[i * MAXKT + t];
                for (int h = 0; h < HID; ++h)
                    a += gh[r][h] * fw[((size_t)i * HID + h) * MAXKT + t];
                lg[rowg * 32 + t] = a;
            }
        }
        __syncthreads();
    }
    if (tid < kt) {
        float mx = -FLT_MAX;
        for (int r = 0; r < m; ++r) mx = fmaxf(mx, lg[r * 32 + tid] * cs);
        float z = 0.f;
        for (int r = 0; r < m; ++r) {
            float e = expf(lg[r * 32 + tid] * cs - mx);
            lg[r * 32 + tid] = e; z += e;
        }
        float iz = 1.f / z;
        for (int r = 0; r < m; ++r) lg[r * 32 + tid] *= iz;
    }
    __syncthreads();
    float accA[29], accB[29];
#pragma unroll
    for (int t = 0; t < 29; ++t) { accA[t] = 0.f; accB[t] = 0.f; }
    for (int r = 0; r < m; ++r) {
        float xa = capi[(size_t)(1 + r) * EMB + tid];
        float xb = capi[(size_t)(1 + r) * EMB + tid + 256];
#pragma unroll
        for (int t = 0; t < 29; ++t) {
            if (t < kt) { float w = lg[r * 32 + t]; accA[t] += w * xa; accB[t] += w * xb; }
        }
    }
    __syncthreads();
    float* rowsb = w1s;
    rowsb[tid] = capi[tid];
    rowsb[tid + 256] = capi[tid + 256];
#pragma unroll
    for (int t = 0; t < 29; ++t) {
        if (t < kt) {
            rowsb[(1 + t) * 513 + tid] = accA[t];
            rowsb[(1 + t) * 513 + tid + 256] = accB[t];
        }
    }
    __syncthreads();
    {
        int rrow = tid & 31, q = tid >> 5;
        float s = 0.f;
        if (rrow <= kt) {
            const float* rp = rowsb + rrow * 513 + q * 64;
            for (int k = 0; k < 64; ++k) s += rp[k] * rp[k];
        }
        pb2[q * 32 + rrow] = s;
    }
    __syncthreads();
    if (tid < 32 && tid <= kt) {
        float s = 0.f;
#pragma unroll
        for (int q = 0; q < 8; ++q) s += pb2[q * 32 + tid];
        inv2[tid] = 1.f / fmaxf(sqrtf(s), 1e-12f);
    }
    __syncthreads();
    for (int t = 0; t <= kt; ++t) {
        float iv = inv2[t];
        g_selcap[((size_t)i * 30 + t) * EMB + tid] = rowsb[t * 513 + tid] * iv;
        g_selcap[((size_t)i * 30 + t) * EMB + tid + 256] = rowsb[t * 513 + tid + 256] * iv;
    }
    if (tid == 0) g_nt[i] = kt + 1;
}

// ---------------- K4: register-tiled score GEMM (block = 1 image) ----------------
__global__ void __launch_bounds__(256) k4_score(const float* __restrict__ img) {
    extern __shared__ float sh4[];
    float* cgT = sh4;                 // [512][64]
    float* xs  = sh4 + 512 * 64;      // [32][513]
    int b = blockIdx.x, tid = threadIdx.x;
    for (int v = tid; v < BT * EMB; v += 256) {
        int cp = v >> 9, c = v & 511;
        cgT[c * 64 + cp] = g_capglo[v];
    }
    __syncthreads();
    int capg = tid & 15;      // 4 captions: capg*4 ..
    int rowg = tid >> 4;      // 2 rows: rowg*2 ..
    for (int chunk = 0; chunk < 7; ++chunk) {
        int jbase = chunk * 32;
        for (int v = tid; v < 32 * 512; v += 256) {
            int r = v >> 9, c = v & 511;
            int j = jbase + r;
            xs[r * 513 + c] = (j < NP) ? img[((size_t)(b * NR) + 1 + j) * EMB + c] : 0.f;
        }
        __syncthreads();
        ull a00 = 0, a01 = 0, a10 = 0, a11 = 0;
        const float* cgp = cgT + capg * 4;
        const float* x0p = xs + (rowg * 2) * 513;
        const float* x1p = x0p + 513;
        for (int c = 0; c < 512; ++c) {
            ull cgA = *(const ull*)(cgp + c * 64);
            ull cgB = *(const ull*)(cgp + c * 64 + 2);
            float x0 = x0p[c], x1 = x1p[c];
            ull X0 = pk2(x0, x0), X1 = pk2(x1, x1);
            fma2(a00, X0, cgA); fma2(a01, X0, cgB);
            fma2(a10, X1, cgA); fma2(a11, X1, cgB);
        }
#pragma unroll
        for (int r = 0; r < 2; ++r) {
            int j = jbase + rowg * 2 + r;
            if (j < NP) {
                float inv = g_inv[b * NR + 1 + j];
                float slf = g_self[b * NP + j];
                float2 pA = upk2(r ? a10 : a00);
                float2 pB = upk2(r ? a11 : a01);
                int cap0 = capg * 4;
                g_score[((size_t)(cap0 + 0) * BV + b) * NP + j] = slf + pA.x * inv;
                g_score[((size_t)(cap0 + 1) * BV + b) * NP + j] = slf + pA.y * inv;
                g_score[((size_t)(cap0 + 2) * BV + b) * NP + j] = slf + pB.x * inv;
                g_score[((size_t)(cap0 + 3) * BV + b) * NP + j] = slf + pB.y * inv;
            }
        }
        __syncthreads();
    }
}

// ---------------- K5: per (caption, image) pair ----------------
__global__ void __launch_bounds__(256, 1) k5_pair(
    const float* __restrict__ img, const float* __restrict__ tasc_p,
    float* __restrict__ out) {
    extern __shared__ float dsm[];
    float* R = dsm;                          // 60*512 floats
    float2* Wd = (float2*)(dsm + TOK * EMB); // 118*58 float2 (w,w)
    __shared__ float sc[256];
    __shared__ unsigned keyArr[256];
    __shared__ int keptidx[NKEEP];
    __shared__ int nonidx[NNON];
    __shared__ int cnts[2];
    __shared__ float2 wnon2[NNON];
    __shared__ float red[32];
    __shared__ float rinv[TOK];
    __shared__ float simbuf[30 * TOK];
    int tid = threadIdx.x;
    int i = blockIdx.x, b = blockIdx.y;
    const float* imb = img + (size_t)b * NR * EMB;

    float v = (tid < NP) ? g_score[((size_t)i * BV + b) * NP + tid] : 0.f;
    unsigned key = (tid < NP) ? f2k(v) : 0u;
    sc[tid] = v;
    keyArr[tid] = key;
    if (tid == 0) { cnts[0] = 0; cnts[1] = 0; }

    // radix select: 118th largest key
    unsigned mask = 0, prefix = 0;
    int krem = NKEEP;
    for (int bb = 31; bb >= 0; --bb) {
        unsigned bit = 1u << bb;
        bool pred = ((key & mask) == prefix) && (key & bit);
        int cnt = __syncthreads_count(pred);
        if (cnt >= krem) prefix |= bit; else krem -= cnt;
        mask |= bit;
    }
    // partition
    bool isKept = false;
    if (tid < NP) {
        if (key > prefix) isKept = true;
        else if (key == prefix) {
            int r = 0;
            for (int j = 0; j < tid; ++j) if (keyArr[j] == prefix) ++r;
            isKept = (r < krem);
        }
        if (isKept) { int p = atomicAdd(&cnts[0], 1); keptidx[p] = tid; }
        else        { int p = atomicAdd(&cnts[1], 1); nonidx[p] = tid; }
    }
    // threshold value for softmax shift (all non-kept <= thrf)
    unsigned tu = (prefix & 0x80000000u) ? (prefix & 0x7FFFFFFFu) : ~prefix;
    float thrf = __uint_as_float(tu);
    __syncthreads();

    // non-kept softmax weights
    float e = 0.f;
    if (tid < NNON) {
        e = expf(sc[nonidx[tid]] - thrf);
        wnon2[tid] = make_float2(e, e);
    }
    float nsum = bsum(tid < NNON ? e : 0.f, red);
    float invns = 1.f / nsum;

    // row 0 (cls) + extra row (59), thread owns float2 column index tid
    {
        const float2* imb2 = (const float2*)imb;
        ull acc = 0;
#pragma unroll 4
        for (int q = 0; q < NNON; ++q) {
            ull x = *(const ull*)((const float2*)(imb + (size_t)(1 + nonidx[q]) * EMB) + tid);
            ull w = *(const ull*)(&wnon2[q]);
            fma2(acc, x, w);
        }
        float2 ev = upk2(acc);
        ((float2*)(R + 59 * EMB))[tid] = make_float2(ev.x * invns, ev.y * invns);
        ((float2*)R)[tid] = imb2[tid];
    }

    // load logits (scaled) into Wd.x
    float tasc = tasc_p[0];
    for (int v2 = tid; v2 < NKEEP * KP; v2 += 256) {
        int n = v2 / KP, p = v2 - n * KP;
        Wd[n * KP + p].x = g_logits[((size_t)(b * NP) + keptidx[n]) * KP + p] * tasc;
    }
    __syncthreads();
    // softmax over kept (n) per p, store duplicated (w,w)
    if (tid < KP) {
        float mx = -FLT_MAX;
        for (int n = 0; n < NKEEP; ++n) mx = fmaxf(mx, Wd[n * KP + tid].x);
        float z = 0.f;
        for (int n = 0; n < NKEEP; ++n) {
            float ee = expf(Wd[n * KP + tid].x - mx);
            Wd[n * KP + tid].x = ee; z += ee;
        }
        float iz = 1.f / z;
        for (int n = 0; n < NKEEP; ++n) {
            float w = Wd[n * KP + tid].x * iz;
            Wd[n * KP + tid] = make_float2(w, w);
        }
    }
    __syncthreads();

    // aggr: thread = (H = p-half, c2 = float2 col), 29 p x 4 cols via f32x2
    {
        int H = tid >> 7;
        int c2 = tid & 127;
        ull acc01[29], acc23[29];
#pragma unroll
        for (int t = 0; t < 29; ++t) { acc01[t] = 0; acc23[t] = 0; }
        const float2* xr2 = (const float2*)(imb + (size_t)(1 + keptidx[0]) * EMB);
        ull nX01 = *(const ull*)(xr2 + c2);
        ull nX23 = *(const ull*)(xr2 + c2 + 128);
        const ull* wbase = (const ull*)Wd + H * 29;
        for (int n = 0; n < NKEEP; ++n) {
            ull X01 = nX01, X23 = nX23;
            if (n + 1 < NKEEP) {
                const float2* nx = (const float2*)(imb + (size_t)(1 + keptidx[n + 1]) * EMB);
                nX01 = *(const ull*)(nx + c2);
                nX23 = *(const ull*)(nx + c2 + 128);
            }
            const ull* wrow = wbase + n * KP;
#pragma unroll
            for (int t = 0; t < 29; ++t) {
                ull ww = wrow[t];
                fma2(acc01[t], X01, ww);
                fma2(acc23[t], X23, ww);
            }
        }
#pragma unroll
        for (int t = 0; t < 29; ++t) {
            int p = H * 29 + t;
            float2* rr = (float2*)(R + (size_t)(1 + p) * EMB);
            rr[c2] = upk2(acc01[t]);
            rr[c2 + 128] = upk2(acc23[t]);
        }
    }
    __syncthreads();

    // row inverse norms
    int wid = tid >> 5, lane = tid & 31;
    for (int rrow = wid; rrow < TOK; rrow += 8) {
        const float* rp = R + rrow * EMB;
        float s = 0.f;
        for (int c = lane; c < EMB; c += 32) { float x = rp[c]; s += x * x; }
        for (int o = 16; o; o >>= 1) s += __shfl_down_sync(0xffffffffu, s, o);
        if (lane == 0) rinv[rrow] = 1.f / fmaxf(sqrtf(s), 1e-12f);
    }
    __syncthreads();

    // sim: warp per (t, tok) pair, f32x2 dot
    int T = g_nt[i];
    const float* scap = g_selcap + (size_t)i * 30 * EMB;
    int npair = T * TOK;
    for (int pr = wid; pr < npair; pr += 8) {
        int t = pr / TOK, tok = pr - t * TOK;
        const ull* cv = (const ull*)(scap + (size_t)t * EMB);
        const ull* rv = (const ull*)(R + (size_t)tok * EMB);
        ull acc = 0;
#pragma unroll
        for (int q = 0; q < 8; ++q) {
            int idx = lane + q * 32;
            fma2(acc, cv[idx], rv[idx]);
        }
        float2 av = upk2(acc);
        float s = av.x + av.y;
        for (int o = 16; o; o >>= 1) s += __shfl_down_sync(0xffffffffu, s, o);
        if (lane == 0) simbuf[t * TOK + tok] = s * rinv[tok];
    }
    __syncthreads();
    if (tid < T) {
        float mx = -FLT_MAX;
        for (int tok = 0; tok < TOK; ++tok) mx = fmaxf(mx, simbuf[tid * TOK + tok]);
        simbuf[tid * TOK] = mx;
    }
    __syncthreads();
    if (tid == 0) {
        float s = 0.f;
        for (int t = 0; t < T; ++t) s += simbuf[t * TOK];
        out[b * BT + i] = s / (float)T;
    }
}

extern "C" void kernel_launch(void* const* d_in, const int* in_sizes, int n_in,
                              void* d_out, int out_size) {
    const float* img   = (const float*)d_in[0];
    const float* cap   = (const float*)d_in[1];
    const int*   lens  = (const int*)d_in[2];
    const float* talng = (const float*)d_in[3];
    const float* talnb = (const float*)d_in[4];
    const float* taw1  = (const float*)d_in[5];
    const float* tab1  = (const float*)d_in[6];
    const float* taw2  = (const float*)d_in[7];
    const float* tab2  = (const float*)d_in[8];
    const float* tasc  = (const float*)d_in[9];
    const float* calng = (const float*)d_in[10];
    const float* calnb = (const float*)d_in[11];
    const float* caw1  = (const float*)d_in[12];
    const float* cab1  = (const float*)d_in[13];
    const float* casc  = (const float*)d_in[14];
    const float* fw    = (const float*)d_in[15];
    const float* fb    = (const float*)d_in[16];
    float* out = (float*)d_out;

    cudaFuncSetAttribute(k2_logits, cudaFuncAttributeMaxDynamicSharedMemorySize, 208896);
    cudaFuncSetAttribute(k3_cap,    cudaFuncAttributeMaxDynamicSharedMemorySize, 208896);
    cudaFuncSetAttribute(k4_score,  cudaFuncAttributeMaxDynamicSharedMemorySize, 196736);
    cudaFuncSetAttribute(k5_pair,   cudaFuncAttributeMaxDynamicSharedMemorySize, 177632);

    k1_img<<<BV, 256>>>(img);
    k2_logits<<<392, 256, 208896>>>(img, talng, talnb, taw1, tab1, taw2, tab2);
    k3_cap<<<BT, 256, 208896>>>(cap, lens, calng, calnb, caw1, cab1, casc, fw, fb);
    k4_score<<<BV, 256, 196736>>>(img);
    k5_pair<<<dim3(BT, BV), 256, 177632>>>(img, tasc, out);
}

// round 5
// speedup vs baseline: 1.0265x; 1.0265x over previous
#include <cuda_runtime.h>
#include <cuda_bf16.h>
#include <float.h>
#include <math.h>

#define BV 128
#define BT 64
#define EMB 512
#define NP 196
#define NR 197
#define NKEEP 118
#define NNON 78
#define KP 58
#define HID 102
#define MAXKT 100
#define TOK 60

typedef unsigned long long ull;

__device__ float g_inv[BV * NR];
__device__ float g_self[BV * NP];
__device__ float g_logits[BV * NP * KP];
__device__ float g_capglo[BT * EMB];
__device__ float g_selcap[BT * 30 * EMB];
__device__ int   g_nt[BT];
__device__ float g_score[BT * BV * NP];

__device__ __forceinline__ float gelu_f(float x) {
    return 0.5f * x * (1.0f + erff(x * 0.70710678118654752440f));
}
__device__ __forceinline__ ull pk2(float lo, float hi) {
    ull r; asm("mov.b64 %0,{%1,%2};" : "=l"(r) : "f"(lo), "f"(hi)); return r;
}
__device__ __forceinline__ void fma2(ull& a, ull x, ull w) {
    asm("fma.rn.f32x2 %0,%1,%2,%0;" : "+l"(a) : "l"(x), "l"(w));
}
__device__ __forceinline__ float2 upk2(ull a) {
    float lo, hi; asm("mov.b64 {%0,%1},%2;" : "=f"(lo), "=f"(hi) : "l"(a));
    return make_float2(lo, hi);
}
__device__ __forceinline__ unsigned f2k(float f) {
    unsigned u = __float_as_uint(f);
    return (u & 0x80000000u) ? ~u : (u | 0x80000000u);
}

__device__ __forceinline__ float bsum(float v, float* buf) {
    for (int o = 16; o; o >>= 1) v += __shfl_down_sync(0xffffffffu, v, o);
    int w = threadIdx.x >> 5, l = threadIdx.x & 31;
    if (l == 0) buf[w] = v;
    __syncthreads();
    float r = (threadIdx.x < 8) ? buf[threadIdx.x] : 0.0f;
    if (w == 0) {
        for (int o = 4; o; o >>= 1) r += __shfl_down_sync(0xffffffffu, r, o);
        if (l == 0) buf[0] = r;
    }
    __syncthreads();
    float res = buf[0];
    __syncthreads();
    return res;
}

__device__ __forceinline__ float bsum512(float v, float* buf) {
    for (int o = 16; o; o >>= 1) v += __shfl_down_sync(0xffffffffu, v, o);
    int w = threadIdx.x >> 5, l = threadIdx.x & 31;
    if (l == 0) buf[w] = v;
    __syncthreads();
    float r = (threadIdx.x < 16) ? buf[threadIdx.x] : 0.0f;
    if (w == 0) {
        for (int o = 8; o; o >>= 1) r += __shfl_down_sync(0xffffffffu, r, o);
        if (l == 0) buf[0] = r;
    }
    __syncthreads();
    float res = buf[0];
    __syncthreads();
    return res;
}

// ---------------- K1 ----------------
__global__ void __launch_bounds__(256) k1_img(const float* __restrict__ img) {
    int b = blockIdx.x;
    const float* base = img + (size_t)b * NR * EMB;
    __shared__ float sm[EMB];
    __shared__ float red[32];
    int tid = threadIdx.x;
    for (int c = tid; c < EMB; c += 256) {
        float s = 0.f;
        for (int j = 1; j < NR; ++j) s += base[(size_t)j * EMB + c];
        sm[c] = s * (1.0f / NP);
    }
    __syncthreads();
    float pv = 0.f;
    for (int c = tid; c < EMB; c += 256) { float v = sm[c]; pv += v * v; }
    float nn = bsum(pv, red);
    float rn = 1.f / fmaxf(sqrtf(nn), 1e-12f);
    for (int c = tid; c < EMB; c += 256) sm[c] *= rn;
    __syncthreads();
    int wid = tid >> 5, lane = tid & 31;
    for (int j = wid; j < NR; j += 8) {
        const float* r = base + (size_t)j * EMB;
        float s2 = 0.f, sd = 0.f;
        for (int k = lane; k < EMB; k += 32) { float v = r[k]; s2 += v * v; sd += v * sm[k]; }
        for (int o = 16; o; o >>= 1) {
            s2 += __shfl_down_sync(0xffffffffu, s2, o);
            sd += __shfl_down_sync(0xffffffffu, sd, o);
        }
        if (lane == 0) {
            float inv = 1.f / fmaxf(sqrtf(s2), 1e-12f);
            g_inv[b * NR + j] = inv;
            if (j >= 1) g_self[b * NP + j - 1] = sd * inv;
        }
    }
}

// ---------------- K2 ----------------
__global__ void __launch_bounds__(256) k2_logits(
    const float* __restrict__ img,
    const float* __restrict__ lng, const float* __restrict__ lnb,
    const float* __restrict__ w1, const float* __restrict__ b1,
    const float* __restrict__ w2, const float* __restrict__ b2) {
    extern __shared__ float w1s[];
    __shared__ float ln[2][EMB];
    __shared__ float gh[2][HID];
    __shared__ float red[32];
    int tid = threadIdx.x;
    for (int v = tid; v < EMB * HID; v += 256) w1s[v] = w1[v];
    int base = blockIdx.x * 64;
    for (int rr = 0; rr < 64; rr += 2) {
        __syncthreads();
        for (int r = 0; r < 2; ++r) {
            int grow = base + rr + r;
            int b = grow / NP, j = grow - b * NP;
            const float* src = img + ((size_t)(b * NR) + 1 + j) * EMB;
            for (int c = tid; c < EMB; c += 256) ln[r][c] = src[c];
        }
        __syncthreads();
        for (int r = 0; r < 2; ++r) {
            float p = 0.f;
            for (int c = tid; c < EMB; c += 256) p += ln[r][c];
            float mu = bsum(p, red) * (1.0f / EMB);
            p = 0.f;
            for (int c = tid; c < EMB; c += 256) { float d = ln[r][c] - mu; p += d * d; }
            float var = bsum(p, red) * (1.0f / EMB);
            float rstd = rsqrtf(var + 1e-5f);
            for (int c = tid; c < EMB; c += 256)
                ln[r][c] = (ln[r][c] - mu) * rstd * lng[c] + lnb[c];
            __syncthreads();
        }
        if (tid < 2 * HID) {
            int r = tid >= HID ? 1 : 0;
            int h = tid - r * HID;
            float a = 0.f;
            for (int c = 0; c < EMB; ++c) a += ln[r][c] * w1s[c * HID + h];
            gh[r][h] = gelu_f(a + b1[h]);
        }
        __syncthreads();
        if (tid < 2 * KP) {
            int r = tid >= KP ? 1 : 0;
            int p = tid - r * KP;
            float a = b2[p];
            for (int h = 0; h < HID; ++h) a += gh[r][h] * w2[h * KP + p];
            g_logits[(size_t)(base + rr + r) * KP + p] = a;
        }
    }
}

// ---------------- K3 ----------------
__global__ void __launch_bounds__(256) k3_cap(
    const float* __restrict__ cap, const int* __restrict__ lens,
    const float* __restrict__ lng, const float* __restrict__ lnb,
    const float* __restrict__ w1, const float* __restrict__ b1,
    const float* __restrict__ casc, const float* __restrict__ fw,
    const float* __restrict__ fb) {
    extern __shared__ float w1s[];
    __shared__ float ln[2][EMB];
    __shared__ float gh[2][HID];
    __shared__ float lg[60 * 32];
    __shared__ float red[32];
    __shared__ float pb2[256];
    __shared__ float inv2[32];
    int i = blockIdx.x, tid = threadIdx.x;
    int n = lens[i], m = n - 1;
    int kt = m >> 1;
    kt = kt < 4 ? 4 : kt;
    kt = kt > MAXKT ? MAXKT : kt;
    if (kt > 29) kt = 29;
    const float* capi = cap + (size_t)i * 60 * EMB;
    for (int c = tid; c < EMB; c += 256) {
        float s = 0.f;
        for (int r = 0; r < n; ++r) s += capi[(size_t)r * EMB + c];
        ln[0][c] = s / (float)n;
    }
    __syncthreads();
    float pv = 0.f;
    for (int c = tid; c < EMB; c += 256) pv += ln[0][c] * ln[0][c];
    float nn = bsum(pv, red);
    float rn = 1.f / fmaxf(sqrtf(nn), 1e-12f);
    for (int c = tid; c < EMB; c += 256) g_capglo[i * EMB + c] = ln[0][c] * rn;
    for (int v = tid; v < EMB * HID; v += 256) w1s[v] = w1[v];
    __syncthreads();
    float cs = casc[0];
    for (int rw = 0; rw < m; rw += 2) {
        for (int r = 0; r < 2; ++r) {
            int wi = rw + r < m ? rw + r : m - 1;
            const float* src = capi + (size_t)(1 + wi) * EMB;
            for (int c = tid; c < EMB; c += 256) ln[r][c] = src[c];
        }
        __syncthreads();
        for (int r = 0; r < 2; ++r) {
            float p = 0.f;
            for (int c = tid; c < EMB; c += 256) p += ln[r][c];
            float mu = bsum(p, red) * (1.0f / EMB);
            p = 0.f;
            for (int c = tid; c < EMB; c += 256) { float d = ln[r][c] - mu; p += d * d; }
            float var = bsum(p, red) * (1.0f / EMB);
            float rstd = rsqrtf(var + 1e-5f);
            for (int c = tid; c < EMB; c += 256)
                ln[r][c] = (ln[r][c] - mu) * rstd * lng[c] + lnb[c];
            __syncthreads();
        }
        if (tid < 2 * HID) {
            int r = tid >= HID ? 1 : 0;
            int h = tid - r * HID;
            float a = 0.f;
            for (int c = 0; c < EMB; ++c) a += ln[r][c] * w1s[c * HID + h];
            gh[r][h] = gelu_f(a + b1[h]);
        }
        __syncthreads();
        if (tid < 64) {
            int r = tid >> 5, t = tid & 31;
            int rowg = rw + r;
            if (t < kt && rowg < m) {
                float a = fb[i * MAXKT + t];
                for (int h = 0; h < HID; ++h)
                    a += gh[r][h] * fw[((size_t)i * HID + h) * MAXKT + t];
                lg[rowg * 32 + t] = a;
            }
        }
        __syncthreads();
    }
    if (tid < kt) {
        float mx = -FLT_MAX;
        for (int r = 0; r < m; ++r) mx = fmaxf(mx, lg[r * 32 + tid] * cs);
        float z = 0.f;
        for (int r = 0; r < m; ++r) {
            float e = expf(lg[r * 32 + tid] * cs - mx);
            lg[r * 32 + tid] = e; z += e;
        }
        float iz = 1.f / z;
        for (int r = 0; r < m; ++r) lg[r * 32 + tid] *= iz;
    }
    __syncthreads();
    float accA[29], accB[29];
#pragma unroll
    for (int t = 0; t < 29; ++t) { accA[t] = 0.f; accB[t] = 0.f; }
    for (int r = 0; r < m; ++r) {
        float xa = capi[(size_t)(1 + r) * EMB + tid];
        float xb = capi[(size_t)(1 + r) * EMB + tid + 256];
#pragma unroll
        for (int t = 0; t < 29; ++t) {
            if (t < kt) { float w = lg[r * 32 + t]; accA[t] += w * xa; accB[t] += w * xb; }
        }
    }
    __syncthreads();
    float* rowsb = w1s;
    rowsb[tid] = capi[tid];
    rowsb[tid + 256] = capi[tid + 256];
#pragma unroll
    for (int t = 0; t < 29; ++t) {
        if (t < kt) {
            rowsb[(1 + t) * 513 + tid] = accA[t];
            rowsb[(1 + t) * 513 + tid + 256] = accB[t];
        }
    }
    __syncthreads();
    {
        int rrow = tid & 31, q = tid >> 5;
        float s = 0.f;
        if (rrow <= kt) {
            const float* rp = rowsb + rrow * 513 + q * 64;
            for (int k = 0; k < 64; ++k) s += rp[k] * rp[k];
        }
        pb2[q * 32 + rrow] = s;
    }
    __syncthreads();
    if (tid < 32 && tid <= kt) {
        float s = 0.f;
#pragma unroll
        for (int q = 0; q < 8; ++q) s += pb2[q * 32 + tid];
        inv2[tid] = 1.f / fmaxf(sqrtf(s), 1e-12f);
    }
    __syncthreads();
    for (int t = 0; t <= kt; ++t) {
        float iv = inv2[t];
        g_selcap[((size_t)i * 30 + t) * EMB + tid] = rowsb[t * 513 + tid] * iv;
        g_selcap[((size_t)i * 30 + t) * EMB + tid + 256] = rowsb[t * 513 + tid + 256] * iv;
    }
    if (tid == 0) g_nt[i] = kt + 1;
}

// ---------------- K4 ----------------
__global__ void __launch_bounds__(256) k4_score(const float* __restrict__ img) {
    extern __shared__ float sh4[];
    float* cgT = sh4;
    float* xs  = sh4 + 512 * 64;
    int b = blockIdx.x, tid = threadIdx.x;
    for (int v = tid; v < BT * EMB; v += 256) {
        int cp = v >> 9, c = v & 511;
        cgT[c * 64 + cp] = g_capglo[v];
    }
    __syncthreads();
    int capg = tid & 15;
    int rowg = tid >> 4;
    for (int chunk = 0; chunk < 7; ++chunk) {
        int jbase = chunk * 32;
        for (int v = tid; v < 32 * 512; v += 256) {
            int r = v >> 9, c = v & 511;
            int j = jbase + r;
            xs[r * 513 + c] = (j < NP) ? img[((size_t)(b * NR) + 1 + j) * EMB + c] : 0.f;
        }
        __syncthreads();
        ull a00 = 0, a01 = 0, a10 = 0, a11 = 0;
        const float* cgp = cgT + capg * 4;
        const float* x0p = xs + (rowg * 2) * 513;
        const float* x1p = x0p + 513;
        for (int c = 0; c < 512; ++c) {
            ull cgA = *(const ull*)(cgp + c * 64);
            ull cgB = *(const ull*)(cgp + c * 64 + 2);
            float x0 = x0p[c], x1 = x1p[c];
            ull X0 = pk2(x0, x0), X1 = pk2(x1, x1);
            fma2(a00, X0, cgA); fma2(a01, X0, cgB);
            fma2(a10, X1, cgA); fma2(a11, X1, cgB);
        }
#pragma unroll
        for (int r = 0; r < 2; ++r) {
            int j = jbase + rowg * 2 + r;
            if (j < NP) {
                float inv = g_inv[b * NR + 1 + j];
                float slf = g_self[b * NP + j];
                float2 pA = upk2(r ? a10 : a00);
                float2 pB = upk2(r ? a11 : a01);
                int cap0 = capg * 4;
                g_score[((size_t)(cap0 + 0) * BV + b) * NP + j] = slf + pA.x * inv;
                g_score[((size_t)(cap0 + 1) * BV + b) * NP + j] = slf + pA.y * inv;
                g_score[((size_t)(cap0 + 2) * BV + b) * NP + j] = slf + pB.x * inv;
                g_score[((size_t)(cap0 + 3) * BV + b) * NP + j] = slf + pB.y * inv;
            }
        }
        __syncthreads();
    }
}

// ---------------- K5: per-pair, 512 threads ----------------
__global__ void __launch_bounds__(512, 1) k5_pair(
    const float* __restrict__ img, const float* __restrict__ tasc_p,
    float* __restrict__ out) {
    extern __shared__ float dsm[];
    float* R = dsm;                          // 60*512
    float2* Wd = (float2*)(dsm + TOK * EMB); // 118*58 (w,w)
    __shared__ float sc[256];
    __shared__ unsigned keyArr[256];
    __shared__ int keptidx[NKEEP];
    __shared__ int nonidx[NNON];
    __shared__ int cnts[2];
    __shared__ float2 wnon2[NNON];
    __shared__ float red[32];
    __shared__ float rinv[TOK];
    __shared__ float simbuf[30 * TOK];
    int tid = threadIdx.x;
    int i = blockIdx.x, b = blockIdx.y;
    const float* imb = img + (size_t)b * NR * EMB;

    float v = (tid < NP) ? g_score[((size_t)i * BV + b) * NP + tid] : 0.f;
    unsigned key = (tid < NP) ? f2k(v) : 0u;
    if (tid < 256) { sc[tid] = v; keyArr[tid] = key; }
    if (tid == 0) { cnts[0] = 0; cnts[1] = 0; }

    // radix select for 118th largest key
    unsigned mask = 0, prefix = 0;
    int krem = NKEEP;
    for (int bb = 31; bb >= 0; --bb) {
        unsigned bit = 1u << bb;
        bool pred = ((key & mask) == prefix) && (key & bit);
        int cnt = __syncthreads_count(pred);
        if (cnt >= krem) prefix |= bit; else krem -= cnt;
        mask |= bit;
    }
    bool isKept = false;
    if (tid < NP) {
        if (key > prefix) isKept = true;
        else if (key == prefix) {
            int r = 0;
            for (int j = 0; j < tid; ++j) if (keyArr[j] == prefix) ++r;
            isKept = (r < krem);
        }
        if (isKept) { int p = atomicAdd(&cnts[0], 1); keptidx[p] = tid; }
        else        { int p = atomicAdd(&cnts[1], 1); nonidx[p] = tid; }
    }
    unsigned tu = (prefix & 0x80000000u) ? (prefix & 0x7FFFFFFFu) : ~prefix;
    float thrf = __uint_as_float(tu);
    __syncthreads();

    float e = 0.f;
    if (tid < NNON) {
        e = expf(sc[nonidx[tid]] - thrf);
        wnon2[tid] = make_float2(e, e);
    }
    float nsum = bsum512(tid < NNON ? e : 0.f, red);
    float invns = 1.f / nsum;

    // cls + extra row: half h sums its half of NNON, combine via simbuf scratch
    {
        int h = tid >> 8, c2 = tid & 255;
        ull acc = 0;
        int q0 = h * 39, q1 = q0 + 39;
        for (int q = q0; q < q1; ++q) {
            ull x = *(const ull*)((const float2*)(imb + (size_t)(1 + nonidx[q]) * EMB) + c2);
            fma2(acc, x, *(const ull*)(&wnon2[q]));
        }
        float2 ev = upk2(acc);
        if (h == 1) { simbuf[c2 * 2] = ev.x; simbuf[c2 * 2 + 1] = ev.y; }
        __syncthreads();
        if (h == 0) {
            ((float2*)(R + 59 * EMB))[c2] =
                make_float2((ev.x + simbuf[c2 * 2]) * invns, (ev.y + simbuf[c2 * 2 + 1]) * invns);
            ((float2*)R)[c2] = ((const float2*)imb)[c2];
        }
    }

    float tasc = tasc_p[0];
    for (int v2 = tid; v2 < NKEEP * 64; v2 += 512) {
        int n = v2 >> 6, p = v2 & 63;
        if (p < KP)
            Wd[n * KP + p].x = g_logits[((size_t)(b * NP) + keptidx[n]) * KP + p] * tasc;
    }
    __syncthreads();

    // kept softmax: warp per p
    int wd = tid >> 5, ln = tid & 31;
    for (int p = wd; p < KP; p += 16) {
        float mx = -FLT_MAX;
        for (int n = ln; n < NKEEP; n += 32) mx = fmaxf(mx, Wd[n * KP + p].x);
        for (int o = 16; o; o >>= 1) mx = fmaxf(mx, __shfl_xor_sync(0xffffffffu, mx, o));
        float z = 0.f;
        for (int n = ln; n < NKEEP; n += 32) {
            float ee = expf(Wd[n * KP + p].x - mx);
            Wd[n * KP + p].x = ee; z += ee;
        }
        for (int o = 16; o; o >>= 1) z += __shfl_xor_sync(0xffffffffu, z, o);
        float iz = 1.f / z;
        for (int n = ln; n < NKEEP; n += 32) {
            float w = Wd[n * KP + p].x * iz;
            Wd[n * KP + p] = make_float2(w, w);
        }
    }
    __syncthreads();

    // aggr: H=tid>>8 selects 29 p-rows, c2=tid&255 one float2 column
    {
        int H = tid >> 8, c2 = tid & 255;
        ull acc[29];
#pragma unroll
        for (int t = 0; t < 29; ++t) acc[t] = 0;
        ull nX = *(const ull*)((const float2*)(imb + (size_t)(1 + keptidx[0]) * EMB) + c2);
        const ull* wbase = (const ull*)Wd + H * 29;
        for (int n = 0; n < NKEEP; ++n) {
            ull X = nX;
            if (n + 1 < NKEEP)
                nX = *(const ull*)((const float2*)(imb + (size_t)(1 + keptidx[n + 1]) * EMB) + c2);
            const ull* wrow = wbase + n * KP;
#pragma unroll
            for (int t = 0; t < 29; ++t) fma2(acc[t], X, wrow[t]);
        }
#pragma unroll
        for (int t = 0; t < 29; ++t)
            ((float2*)(R + (size_t)(1 + H * 29 + t) * EMB))[c2] = upk2(acc[t]);
    }
    __syncthreads();

    for (int r = wd; r < TOK; r += 16) {
        const float* rp = R + r * EMB;
        float s = 0.f;
        for (int c = ln; c < EMB; c += 32) { float x = rp[c]; s += x * x; }
        for (int o = 16; o; o >>= 1) s += __shfl_down_sync(0xffffffffu, s, o);
        if (ln == 0) rinv[r] = 1.f / fmaxf(sqrtf(s), 1e-12f);
    }
    __syncthreads();

    int T = g_nt[i];
    const float* scap = g_selcap + (size_t)i * 30 * EMB;
    int npair = T * TOK;
    for (int pr = wd; pr < npair; pr += 16) {
        int t = pr / TOK, tok = pr - t * TOK;
        const ull* cv = (const ull*)(scap + (size_t)t * EMB);
        const ull* rv = (const ull*)(R + (size_t)tok * EMB);
        ull a = 0;
#pragma unroll
        for (int q = 0; q < 8; ++q) fma2(a, cv[ln + q * 32], rv[ln + q * 32]);
        float2 av = upk2(a);
        float s = av.x + av.y;
        for (int o = 16; o; o >>= 1) s += __shfl_down_sync(0xffffffffu, s, o);
        if (ln == 0) simbuf[t * TOK + tok] = s * rinv[tok];
    }
    __syncthreads();
    if (tid < T) {
        float mx = -FLT_MAX;
        for (int tok = 0; tok < TOK; ++tok) mx = fmaxf(mx, simbuf[tid * TOK + tok]);
        simbuf[tid * TOK] = mx;
    }
    __syncthreads();
    if (tid == 0) {
        float s = 0.f;
        for (int t = 0; t < T; ++t) s += simbuf[t * TOK];
        out[b * BT + i] = s / (float)T;
    }
}

extern "C" void kernel_launch(void* const* d_in, const int* in_sizes, int n_in,
                              void* d_out, int out_size) {
    const float* img   = (const float*)d_in[0];
    const float* cap   = (const float*)d_in[1];
    const int*   lens  = (const int*)d_in[2];
    const float* talng = (const float*)d_in[3];
    const float* talnb = (const float*)d_in[4];
    const float* taw1  = (const float*)d_in[5];
    const float* tab1  = (const float*)d_in[6];
    const float* taw2  = (const float*)d_in[7];
    const float* tab2  = (const float*)d_in[8];
    const float* tasc  = (const float*)d_in[9];
    const float* calng = (const float*)d_in[10];
    const float* calnb = (const float*)d_in[11];
    const float* caw1  = (const float*)d_in[12];
    const float* cab1  = (const float*)d_in[13];
    const float* casc  = (const float*)d_in[14];
    const float* fw    = (const float*)d_in[15];
    const float* fb    = (const float*)d_in[16];
    float* out = (float*)d_out;

    cudaFuncSetAttribute(k2_logits, cudaFuncAttributeMaxDynamicSharedMemorySize, 208896);
    cudaFuncSetAttribute(k3_cap,    cudaFuncAttributeMaxDynamicSharedMemorySize, 208896);
    cudaFuncSetAttribute(k4_score,  cudaFuncAttributeMaxDynamicSharedMemorySize, 196736);
    cudaFuncSetAttribute(k5_pair,   cudaFuncAttributeMaxDynamicSharedMemorySize, 177632);

    k1_img<<<BV, 256>>>(img);
    k2_logits<<<392, 256, 208896>>>(img, talng, talnb, taw1, tab1, taw2, tab2);
    k3_cap<<<BT, 256, 208896>>>(cap, lens, calng, calnb, caw1, cab1, casc, fw, fb);
    k4_score<<<BV, 256, 196736>>>(img);
    k5_pair<<<dim3(BT, BV), 512, 177632>>>(img, tasc, out);
}

// round 6
// speedup vs baseline: 1.6516x; 1.6090x over previous
#include <cuda_runtime.h>
#include <cuda_bf16.h>
#include <float.h>
#include <math.h>

#define BV 128
#define BT 64
#define EMB 512
#define NP 196
#define NR 197
#define NKEEP 118
#define NNON 78
#define KP 58
#define HID 102
#define MAXKT 100
#define TOK 60
#define RS 516
#define WSOFF 33024
#define XSOFF 41472

typedef unsigned long long ull;

__device__ float g_inv[BV * NR];
__device__ float g_self[BV * NP];
__device__ float g_logits[BV * NP * KP];
__device__ float g_capglo[BT * EMB];
__device__ float g_selcap[BT * 32 * EMB];
__device__ int   g_nt[BT];
__device__ float g_score[BT * BV * NP];

__device__ __forceinline__ float gelu_f(float x) {
    return 0.5f * x * (1.0f + erff(x * 0.70710678118654752440f));
}
__device__ __forceinline__ ull pk2(float lo, float hi) {
    ull r; asm("mov.b64 %0,{%1,%2};" : "=l"(r) : "f"(lo), "f"(hi)); return r;
}
__device__ __forceinline__ void fma2(ull& a, ull x, ull w) {
    asm("fma.rn.f32x2 %0,%1,%2,%0;" : "+l"(a) : "l"(x), "l"(w));
}
__device__ __forceinline__ float2 upk2(ull a) {
    float lo, hi; asm("mov.b64 {%0,%1},%2;" : "=f"(lo), "=f"(hi) : "l"(a));
    return make_float2(lo, hi);
}
__device__ __forceinline__ unsigned f2k(float f) {
    unsigned u = __float_as_uint(f);
    return (u & 0x80000000u) ? ~u : (u | 0x80000000u);
}
__device__ __forceinline__ unsigned tf32r(float x) {
    unsigned r; asm("cvt.rna.tf32.f32 %0,%1;" : "=r"(r) : "f"(x)); return r;
}
__device__ __forceinline__ void mma8(float* d, unsigned a0, unsigned a1, unsigned a2,
                                     unsigned a3, unsigned b0, unsigned b1) {
    asm("mma.sync.aligned.m16n8k8.row.col.f32.tf32.tf32.f32 "
        "{%0,%1,%2,%3},{%4,%5,%6,%7},{%8,%9},{%0,%1,%2,%3};"
        : "+f"(d[0]), "+f"(d[1]), "+f"(d[2]), "+f"(d[3])
        : "r"(a0), "r"(a1), "r"(a2), "r"(a3), "r"(b0), "r"(b1));
}

__device__ __forceinline__ float bsum(float v, float* buf) {
    for (int o = 16; o; o >>= 1) v += __shfl_down_sync(0xffffffffu, v, o);
    int w = threadIdx.x >> 5, l = threadIdx.x & 31;
    if (l == 0) buf[w] = v;
    __syncthreads();
    float r = (threadIdx.x < 8) ? buf[threadIdx.x] : 0.0f;
    if (w == 0) {
        for (int o = 4; o; o >>= 1) r += __shfl_down_sync(0xffffffffu, r, o);
        if (l == 0) buf[0] = r;
    }
    __syncthreads();
    float res = buf[0];
    __syncthreads();
    return res;
}
__device__ __forceinline__ float bsum512(float v, float* buf) {
    for (int o = 16; o; o >>= 1) v += __shfl_down_sync(0xffffffffu, v, o);
    int w = threadIdx.x >> 5, l = threadIdx.x & 31;
    if (l == 0) buf[w] = v;
    __syncthreads();
    float r = (threadIdx.x < 16) ? buf[threadIdx.x] : 0.0f;
    if (w == 0) {
        for (int o = 8; o; o >>= 1) r += __shfl_down_sync(0xffffffffu, r, o);
        if (l == 0) buf[0] = r;
    }
    __syncthreads();
    float res = buf[0];
    __syncthreads();
    return res;
}

// ---------------- K1 ----------------
__global__ void __launch_bounds__(256) k1_img(const float* __restrict__ img) {
    int b = blockIdx.x;
    const float* base = img + (size_t)b * NR * EMB;
    __shared__ float sm[EMB];
    __shared__ float red[32];
    int tid = threadIdx.x;
    for (int c = tid; c < EMB; c += 256) {
        float s = 0.f;
        for (int j = 1; j < NR; ++j) s += base[(size_t)j * EMB + c];
        sm[c] = s * (1.0f / NP);
    }
    __syncthreads();
    float pv = 0.f;
    for (int c = tid; c < EMB; c += 256) { float v = sm[c]; pv += v * v; }
    float nn = bsum(pv, red);
    float rn = 1.f / fmaxf(sqrtf(nn), 1e-12f);
    for (int c = tid; c < EMB; c += 256) sm[c] *= rn;
    __syncthreads();
    int wid = tid >> 5, lane = tid & 31;
    for (int j = wid; j < NR; j += 8) {
        const float* r = base + (size_t)j * EMB;
        float s2 = 0.f, sd = 0.f;
        for (int k = lane; k < EMB; k += 32) { float v = r[k]; s2 += v * v; sd += v * sm[k]; }
        for (int o = 16; o; o >>= 1) {
            s2 += __shfl_down_sync(0xffffffffu, s2, o);
            sd += __shfl_down_sync(0xffffffffu, sd, o);
        }
        if (lane == 0) {
            float inv = 1.f / fmaxf(sqrtf(s2), 1e-12f);
            g_inv[b * NR + j] = inv;
            if (j >= 1) g_self[b * NP + j - 1] = sd * inv;
        }
    }
}

// ---------------- K2 ----------------
__global__ void __launch_bounds__(256) k2_logits(
    const float* __restrict__ img,
    const float* __restrict__ lng, const float* __restrict__ lnb,
    const float* __restrict__ w1, const float* __restrict__ b1,
    const float* __restrict__ w2, const float* __restrict__ b2) {
    extern __shared__ float w1s[];
    __shared__ float ln[2][EMB];
    __shared__ float gh[2][HID];
    __shared__ float red[32];
    int tid = threadIdx.x;
    for (int v = tid; v < EMB * HID; v += 256) w1s[v] = w1[v];
    int base = blockIdx.x * 64;
    for (int rr = 0; rr < 64; rr += 2) {
        __syncthreads();
        for (int r = 0; r < 2; ++r) {
            int grow = base + rr + r;
            int b = grow / NP, j = grow - b * NP;
            const float* src = img + ((size_t)(b * NR) + 1 + j) * EMB;
            for (int c = tid; c < EMB; c += 256) ln[r][c] = src[c];
        }
        __syncthreads();
        for (int r = 0; r < 2; ++r) {
            float p = 0.f;
            for (int c = tid; c < EMB; c += 256) p += ln[r][c];
            float mu = bsum(p, red) * (1.0f / EMB);
            p = 0.f;
            for (int c = tid; c < EMB; c += 256) { float d = ln[r][c] - mu; p += d * d; }
            float var = bsum(p, red) * (1.0f / EMB);
            float rstd = rsqrtf(var + 1e-5f);
            for (int c = tid; c < EMB; c += 256)
                ln[r][c] = (ln[r][c] - mu) * rstd * lng[c] + lnb[c];
            __syncthreads();
        }
        if (tid < 2 * HID) {
            int r = tid >= HID ? 1 : 0;
            int h = tid - r * HID;
            float a = 0.f;
            for (int c = 0; c < EMB; ++c) a += ln[r][c] * w1s[c * HID + h];
            gh[r][h] = gelu_f(a + b1[h]);
        }
        __syncthreads();
        if (tid < 2 * KP) {
            int r = tid >= KP ? 1 : 0;
            int p = tid - r * KP;
            float a = b2[p];
            for (int h = 0; h < HID; ++h) a += gh[r][h] * w2[h * KP + p];
            g_logits[(size_t)(base + rr + r) * KP + p] = a;
        }
    }
}

// ---------------- K3 ----------------
__global__ void __launch_bounds__(256) k3_cap(
    const float* __restrict__ cap, const int* __restrict__ lens,
    const float* __restrict__ lng, const float* __restrict__ lnb,
    const float* __restrict__ w1, const float* __restrict__ b1,
    const float* __restrict__ casc, const float* __restrict__ fw,
    const float* __restrict__ fb) {
    extern __shared__ float w1s[];
    __shared__ float ln[2][EMB];
    __shared__ float gh[2][HID];
    __shared__ float lg[60 * 32];
    __shared__ float red[32];
    __shared__ float pb2[256];
    __shared__ float inv2[32];
    int i = blockIdx.x, tid = threadIdx.x;
    int n = lens[i], m = n - 1;
    int kt = m >> 1;
    kt = kt < 4 ? 4 : kt;
    kt = kt > MAXKT ? MAXKT : kt;
    if (kt > 29) kt = 29;
    const float* capi = cap + (size_t)i * 60 * EMB;
    for (int c = tid; c < EMB; c += 256) {
        float s = 0.f;
        for (int r = 0; r < n; ++r) s += capi[(size_t)r * EMB + c];
        ln[0][c] = s / (float)n;
    }
    __syncthreads();
    float pv = 0.f;
    for (int c = tid; c < EMB; c += 256) pv += ln[0][c] * ln[0][c];
    float nn = bsum(pv, red);
    float rn = 1.f / fmaxf(sqrtf(nn), 1e-12f);
    for (int c = tid; c < EMB; c += 256) g_capglo[i * EMB + c] = ln[0][c] * rn;
    for (int v = tid; v < EMB * HID; v += 256) w1s[v] = w1[v];
    __syncthreads();
    float cs = casc[0];
    for (int rw = 0; rw < m; rw += 2) {
        for (int r = 0; r < 2; ++r) {
            int wi = rw + r < m ? rw + r : m - 1;
            const float* src = capi + (size_t)(1 + wi) * EMB;
            for (int c = tid; c < EMB; c += 256) ln[r][c] = src[c];
        }
        __syncthreads();
        for (int r = 0; r < 2; ++r) {
            float p = 0.f;
            for (int c = tid; c < EMB; c += 256) p += ln[r][c];
            float mu = bsum(p, red) * (1.0f / EMB);
            p = 0.f;
            for (int c = tid; c < EMB; c += 256) { float d = ln[r][c] - mu; p += d * d; }
            float var = bsum(p, red) * (1.0f / EMB);
            float rstd = rsqrtf(var + 1e-5f);
            for (int c = tid; c < EMB; c += 256)
                ln[r][c] = (ln[r][c] - mu) * rstd * lng[c] + lnb[c];
            __syncthreads();
        }
        if (tid < 2 * HID) {
            int r = tid >= HID ? 1 : 0;
            int h = tid - r * HID;
            float a = 0.f;
            for (int c = 0; c < EMB; ++c) a += ln[r][c] * w1s[c * HID + h];
            gh[r][h] = gelu_f(a + b1[h]);
        }
        __syncthreads();
        if (tid < 64) {
            int r = tid >> 5, t = tid & 31;
            int rowg = rw + r;
            if (t < kt && rowg < m) {
                float a = fb[i * MAXKT + t];
                for (int h = 0; h < HID; ++h)
                    a += gh[r][h] * fw[((size_t)i * HID + h) * MAXKT + t];
                lg[rowg * 32 + t] = a;
            }
        }
        __syncthreads();
    }
    if (tid < kt) {
        float mx = -FLT_MAX;
        for (int r = 0; r < m; ++r) mx = fmaxf(mx, lg[r * 32 + tid] * cs);
        float z = 0.f;
        for (int r = 0; r < m; ++r) {
            float e = expf(lg[r * 32 + tid] * cs - mx);
            lg[r * 32 + tid] = e; z += e;
        }
        float iz = 1.f / z;
        for (int r = 0; r < m; ++r) lg[r * 32 + tid] *= iz;
    }
    __syncthreads();
    float accA[29], accB[29];
#pragma unroll
    for (int t = 0; t < 29; ++t) { accA[t] = 0.f; accB[t] = 0.f; }
    for (int r = 0; r < m; ++r) {
        float xa = capi[(size_t)(1 + r) * EMB + tid];
        float xb = capi[(size_t)(1 + r) * EMB + tid + 256];
#pragma unroll
        for (int t = 0; t < 29; ++t) {
            if (t < kt) { float w = lg[r * 32 + t]; accA[t] += w * xa; accB[t] += w * xb; }
        }
    }
    __syncthreads();
    float* rowsb = w1s;
    rowsb[tid] = capi[tid];
    rowsb[tid + 256] = capi[tid + 256];
#pragma unroll
    for (int t = 0; t < 29; ++t) {
        if (t < kt) {
            rowsb[(1 + t) * 513 + tid] = accA[t];
            rowsb[(1 + t) * 513 + tid + 256] = accB[t];
        }
    }
    __syncthreads();
    {
        int rrow = tid & 31, q = tid >> 5;
        float s = 0.f;
        if (rrow <= kt) {
            const float* rp = rowsb + rrow * 513 + q * 64;
            for (int k = 0; k < 64; ++k) s += rp[k] * rp[k];
        }
        pb2[q * 32 + rrow] = s;
    }
    __syncthreads();
    if (tid < 32 && tid <= kt) {
        float s = 0.f;
#pragma unroll
        for (int q = 0; q < 8; ++q) s += pb2[q * 32 + tid];
        inv2[tid] = 1.f / fmaxf(sqrtf(s), 1e-12f);
    }
    __syncthreads();
    for (int t = 0; t <= kt; ++t) {
        float iv = inv2[t];
        g_selcap[((size_t)i * 32 + t) * EMB + tid] = rowsb[t * 513 + tid] * iv;
        g_selcap[((size_t)i * 32 + t) * EMB + tid + 256] = rowsb[t * 513 + tid + 256] * iv;
    }
    if (tid == 0) g_nt[i] = kt + 1;
}

// ---------------- K4 ----------------
__global__ void __launch_bounds__(256) k4_score(const float* __restrict__ img) {
    extern __shared__ float sh4[];
    float* cgT = sh4;
    float* xs  = sh4 + 512 * 64;
    int b = blockIdx.x, tid = threadIdx.x;
    for (int v = tid; v < BT * EMB; v += 256) {
        int cp = v >> 9, c = v & 511;
        cgT[c * 64 + cp] = g_capglo[v];
    }
    __syncthreads();
    int capg = tid & 15;
    int rowg = tid >> 4;
    for (int chunk = 0; chunk < 7; ++chunk) {
        int jbase = chunk * 32;
        for (int v = tid; v < 32 * 512; v += 256) {
            int r = v >> 9, c = v & 511;
            int j = jbase + r;
            xs[r * 513 + c] = (j < NP) ? img[((size_t)(b * NR) + 1 + j) * EMB + c] : 0.f;
        }
        __syncthreads();
        ull a00 = 0, a01 = 0, a10 = 0, a11 = 0;
        const float* cgp = cgT + capg * 4;
        const float* x0p = xs + (rowg * 2) * 513;
        const float* x1p = x0p + 513;
        for (int c = 0; c < 512; ++c) {
            ull cgA = *(const ull*)(cgp + c * 64);
            ull cgB = *(const ull*)(cgp + c * 64 + 2);
            float x0 = x0p[c], x1 = x1p[c];
            ull X0 = pk2(x0, x0), X1 = pk2(x1, x1);
            fma2(a00, X0, cgA); fma2(a01, X0, cgB);
            fma2(a10, X1, cgA); fma2(a11, X1, cgB);
        }
#pragma unroll
        for (int r = 0; r < 2; ++r) {
            int j = jbase + rowg * 2 + r;
            if (j < NP) {
                float inv = g_inv[b * NR + 1 + j];
                float slf = g_self[b * NP + j];
                float2 pA = upk2(r ? a10 : a00);
                float2 pB = upk2(r ? a11 : a01);
                int cap0 = capg * 4;
                g_score[((size_t)(cap0 + 0) * BV + b) * NP + j] = slf + pA.x * inv;
                g_score[((size_t)(cap0 + 1) * BV + b) * NP + j] = slf + pA.y * inv;
                g_score[((size_t)(cap0 + 2) * BV + b) * NP + j] = slf + pB.x * inv;
                g_score[((size_t)(cap0 + 3) * BV + b) * NP + j] = slf + pB.y * inv;
            }
        }
        __syncthreads();
    }
}

// ---------------- K5: per-pair with tf32 mma ----------------
__global__ void __launch_bounds__(512, 1) k5_pair(
    const float* __restrict__ img, const float* __restrict__ tasc_p,
    float* __restrict__ out) {
    extern __shared__ float dsm[];
    float* R = dsm;                   // 64 rows x RS(516)
    float* Ws = dsm + WSOFF;          // [64][132] tf32 bits
    float* Xs = dsm + XSOFF;          // 2 x [8][520]
    float* simq = dsm + WSOFF;        // overlay for sim reduction
    __shared__ float sc[256];
    __shared__ unsigned keyArr[256];
    __shared__ int keptidx[NKEEP];
    __shared__ int nonidx[NNON];
    __shared__ int cnts[2];
    __shared__ float2 wnon2[NNON];
    __shared__ float red[32];
    __shared__ float rinv[TOK];
    __shared__ float simbuf[30 * TOK];
    int tid = threadIdx.x;
    int i = blockIdx.x, b = blockIdx.y;
    const float* imb = img + (size_t)b * NR * EMB;

    float v = (tid < NP) ? g_score[((size_t)i * BV + b) * NP + tid] : 0.f;
    unsigned key = (tid < NP) ? f2k(v) : 0u;
    if (tid < 256) { sc[tid] = v; keyArr[tid] = key; }
    if (tid == 0) { cnts[0] = 0; cnts[1] = 0; }
    // zero Ws (also covers padding)
    for (int z = tid; z < 64 * 132; z += 512) Ws[z] = 0.f;

    unsigned mask = 0, prefix = 0;
    int krem = NKEEP;
    for (int bb = 31; bb >= 0; --bb) {
        unsigned bit = 1u << bb;
        bool pred = ((key & mask) == prefix) && (key & bit);
        int cnt = __syncthreads_count(pred);
        if (cnt >= krem) prefix |= bit; else krem -= cnt;
        mask |= bit;
    }
    bool isKept = false;
    if (tid < NP) {
        if (key > prefix) isKept = true;
        else if (key == prefix) {
            int r = 0;
            for (int j = 0; j < tid; ++j) if (keyArr[j] == prefix) ++r;
            isKept = (r < krem);
        }
        if (isKept) { int p = atomicAdd(&cnts[0], 1); keptidx[p] = tid; }
        else        { int p = atomicAdd(&cnts[1], 1); nonidx[p] = tid; }
    }
    unsigned tu = (prefix & 0x80000000u) ? (prefix & 0x7FFFFFFFu) : ~prefix;
    float thrf = __uint_as_float(tu);
    __syncthreads();

    float e = 0.f;
    if (tid < NNON) {
        e = expf(sc[nonidx[tid]] - thrf);
        wnon2[tid] = make_float2(e, e);
    }
    float nsum = bsum512(tid < NNON ? e : 0.f, red);
    float invns = 1.f / nsum;

    // cls (row 0) + extra (row 59)
    {
        int h = tid >> 8, c2 = tid & 255;
        ull acc = 0;
        int q0 = h * 39, q1 = q0 + 39;
        for (int q = q0; q < q1; ++q) {
            ull x = *(const ull*)((const float2*)(imb + (size_t)(1 + nonidx[q]) * EMB) + c2);
            fma2(acc, x, *(const ull*)(&wnon2[q]));
        }
        float2 ev = upk2(acc);
        if (h == 1) { simbuf[c2 * 2] = ev.x; simbuf[c2 * 2 + 1] = ev.y; }
        __syncthreads();
        if (h == 0) {
            ((float2*)(R + 59 * RS))[c2] =
                make_float2((ev.x + simbuf[c2 * 2]) * invns, (ev.y + simbuf[c2 * 2 + 1]) * invns);
            ((float2*)R)[c2] = ((const float2*)imb)[c2];
        }
    }
    __syncthreads();

    // logits -> Ws[p][n]
    float tasc = tasc_p[0];
    for (int v2 = tid; v2 < NKEEP * 64; v2 += 512) {
        int n = v2 >> 6, p = v2 & 63;
        if (p < KP)
            Ws[p * 132 + n] = g_logits[((size_t)(b * NP) + keptidx[n]) * KP + p] * tasc;
    }
    __syncthreads();
    // softmax per p over n, write tf32
    int wq = tid >> 5, ln = tid & 31;
    for (int p = wq; p < KP; p += 16) {
        float* wr = Ws + p * 132;
        float mx = -FLT_MAX;
        for (int n = ln; n < NKEEP; n += 32) mx = fmaxf(mx, wr[n]);
        for (int o = 16; o; o >>= 1) mx = fmaxf(mx, __shfl_xor_sync(0xffffffffu, mx, o));
        float z = 0.f;
        for (int n = ln; n < NKEEP; n += 32) { float ee = expf(wr[n] - mx); wr[n] = ee; z += ee; }
        for (int o = 16; o; o >>= 1) z += __shfl_xor_sync(0xffffffffu, z, o);
        float iz = 1.f / z;
        for (int n = ln; n < NKEEP; n += 32) wr[n] = __uint_as_float(tf32r(wr[n] * iz));
    }

    // ---- aggr mma: D(64x512) = Ws(64x128) @ X(128x512) ----
    {
        int mt = wq & 3, ng = wq >> 2;
        float acc[16][4];
#pragma unroll
        for (int t = 0; t < 16; ++t) { acc[t][0] = acc[t][1] = acc[t][2] = acc[t][3] = 0.f; }
        int srow = tid >> 6, scol = (tid & 63) << 3;
        float4 pa, pb;
        {   // prologue: chunk 0
            int kr = srow;
            if (kr < NKEEP) {
                const float4* s4 = (const float4*)(imb + (size_t)(1 + keptidx[kr]) * EMB + scol);
                pa = s4[0]; pb = s4[1];
            } else { pa = make_float4(0, 0, 0, 0); pb = pa; }
        }
        __syncthreads();   // Ws softmax done
        {
            float* d = Xs + srow * 520 + scol;
            d[0] = __uint_as_float(tf32r(pa.x)); d[1] = __uint_as_float(tf32r(pa.y));
            d[2] = __uint_as_float(tf32r(pa.z)); d[3] = __uint_as_float(tf32r(pa.w));
            d[4] = __uint_as_float(tf32r(pb.x)); d[5] = __uint_as_float(tf32r(pb.y));
            d[6] = __uint_as_float(tf32r(pb.z)); d[7] = __uint_as_float(tf32r(pb.w));
        }
        __syncthreads();
        const unsigned* W32 = (const unsigned*)Ws;
        int arow = mt * 16 + (ln >> 2);
        int kk = ln & 3;
        for (int c = 0; c < 16; ++c) {
            if (c < 15) {
                int kr = (c + 1) * 8 + srow;
                if (kr < NKEEP) {
                    const float4* s4 = (const float4*)(imb + (size_t)(1 + keptidx[kr]) * EMB + scol);
                    pa = s4[0]; pb = s4[1];
                } else { pa = make_float4(0, 0, 0, 0); pb = pa; }
            }
            unsigned a0 = W32[arow * 132 + c * 8 + kk];
            unsigned a1 = W32[(arow + 8) * 132 + c * 8 + kk];
            unsigned a2 = W32[arow * 132 + c * 8 + kk + 4];
            unsigned a3 = W32[(arow + 8) * 132 + c * 8 + kk + 4];
            const unsigned* XB = (const unsigned*)(Xs + (c & 1) * 4160);
            int bc = ng * 128 + (ln >> 2);
#pragma unroll
            for (int nt = 0; nt < 16; ++nt) {
                unsigned b0 = XB[kk * 520 + bc + nt * 8];
                unsigned b1 = XB[(kk + 4) * 520 + bc + nt * 8];
                mma8(acc[nt], a0, a1, a2, a3, b0, b1);
            }
            if (c < 15) {
                float* d = Xs + ((c + 1) & 1) * 4160 + srow * 520 + scol;
                d[0] = __uint_as_float(tf32r(pa.x)); d[1] = __uint_as_float(tf32r(pa.y));
                d[2] = __uint_as_float(tf32r(pa.z)); d[3] = __uint_as_float(tf32r(pa.w));
                d[4] = __uint_as_float(tf32r(pb.x)); d[5] = __uint_as_float(tf32r(pb.y));
                d[6] = __uint_as_float(tf32r(pb.z)); d[7] = __uint_as_float(tf32r(pb.w));
            }
            __syncthreads();
        }
        int r0 = mt * 16 + (ln >> 2);
#pragma unroll
        for (int nt = 0; nt < 16; ++nt) {
            int col = ng * 128 + nt * 8 + 2 * (ln & 3);
            if (r0 < KP) *(float2*)(R + (1 + r0) * RS + col) = make_float2(acc[nt][0], acc[nt][1]);
            if (r0 + 8 < KP) *(float2*)(R + (9 + r0) * RS + col) = make_float2(acc[nt][2], acc[nt][3]);
        }
    }
    __syncthreads();

    // row norms
    for (int r = wq; r < TOK; r += 16) {
        const float* rp = R + r * RS;
        float s = 0.f;
        for (int c = ln; c < EMB; c += 32) { float x = rp[c]; s += x * x; }
        for (int o = 16; o; o >>= 1) s += __shfl_down_sync(0xffffffffu, s, o);
        if (ln == 0) rinv[r] = 1.f / fmaxf(sqrtf(s), 1e-12f);
    }
    __syncthreads();

    // ---- sim mma: selcap(32x512) @ R^T(512x64), 4-way k-split ----
    int T = g_nt[i];
    {
        int ow = wq & 3, ks = wq >> 2;
        int mrow = (ow & 1) * 16 + (ln >> 2);
        int nbase = (ow >> 1) * 32;
        const float* scap = g_selcap + (size_t)i * 32 * EMB;
        float sacc[4][4];
#pragma unroll
        for (int t = 0; t < 4; ++t) { sacc[t][0] = sacc[t][1] = sacc[t][2] = sacc[t][3] = 0.f; }
        for (int kc = 0; kc < 16; ++kc) {
            int k0 = ks * 128 + kc * 8 + (ln & 3);
            unsigned a0 = tf32r(scap[mrow * EMB + k0]);
            unsigned a1 = tf32r(scap[(mrow + 8) * EMB + k0]);
            unsigned a2 = tf32r(scap[mrow * EMB + k0 + 4]);
            unsigned a3 = tf32r(scap[(mrow + 8) * EMB + k0 + 4]);
#pragma unroll
            for (int nt = 0; nt < 4; ++nt) {
                int tok = nbase + nt * 8 + (ln >> 2);
                unsigned b0 = tf32r(R[tok * RS + k0]);
                unsigned b1 = tf32r(R[tok * RS + k0 + 4]);
                mma8(sacc[nt], a0, a1, a2, a3, b0, b1);
            }
        }
        __syncthreads();   // done reading Ws/Xs region; simq overlay safe
        float* q = simq + (ks * 4 + ow) * 512;
        int lr = ln >> 2, lc0 = 2 * (ln & 3);
#pragma unroll
        for (int nt = 0; nt < 4; ++nt) {
            int lc = nt * 8 + lc0;
            q[lr * 32 + lc] = sacc[nt][0]; q[lr * 32 + lc + 1] = sacc[nt][1];
            q[(lr + 8) * 32 + lc] = sacc[nt][2]; q[(lr + 8) * 32 + lc + 1] = sacc[nt][3];
        }
    }
    __syncthreads();
    for (int idx = tid; idx < 2048; idx += 512) {
        int q = idx >> 9, el = idx & 511;
        float s = simq[q * 512 + el] + simq[(4 + q) * 512 + el] +
                  simq[(8 + q) * 512 + el] + simq[(12 + q) * 512 + el];
        int t = (q & 1) * 16 + (el >> 5);
        int tok = (q >> 1) * 32 + (el & 31);
        if (t < T && tok < TOK) simbuf[t * TOK + tok] = s * rinv[tok];
    }
    __syncthreads();
    if (tid < T) {
        float mx = -FLT_MAX;
        for (int tok = 0; tok < TOK; ++tok) mx = fmaxf(mx, simbuf[tid * TOK + tok]);
        simbuf[tid * TOK] = mx;
    }
    __syncthreads();
    if (tid == 0) {
        float s = 0.f;
        for (int t = 0; t < T; ++t) s += simbuf[t * TOK];
        out[b * BT + i] = s / (float)T;
    }
}

extern "C" void kernel_launch(void* const* d_in, const int* in_sizes, int n_in,
                              void* d_out, int out_size) {
    const float* img   = (const float*)d_in[0];
    const float* cap   = (const float*)d_in[1];
    const int*   lens  = (const int*)d_in[2];
    const float* talng = (const float*)d_in[3];
    const float* talnb = (const float*)d_in[4];
    const float* taw1  = (const float*)d_in[5];
    const float* tab1  = (const float*)d_in[6];
    const float* taw2  = (const float*)d_in[7];
    const float* tab2  = (const float*)d_in[8];
    const float* tasc  = (const float*)d_in[9];
    const float* calng = (const float*)d_in[10];
    const float* calnb = (const float*)d_in[11];
    const float* caw1  = (const float*)d_in[12];
    const float* cab1  = (const float*)d_in[13];
    const float* casc  = (const float*)d_in[14];
    const float* fw    = (const float*)d_in[15];
    const float* fb    = (const float*)d_in[16];
    float* out = (float*)d_out;

    cudaFuncSetAttribute(k2_logits, cudaFuncAttributeMaxDynamicSharedMemorySize, 208896);
    cudaFuncSetAttribute(k3_cap,    cudaFuncAttributeMaxDynamicSharedMemorySize, 208896);
    cudaFuncSetAttribute(k4_score,  cudaFuncAttributeMaxDynamicSharedMemorySize, 196736);
    cudaFuncSetAttribute(k5_pair,   cudaFuncAttributeMaxDynamicSharedMemorySize, 199168);

    k1_img<<<BV, 256>>>(img);
    k2_logits<<<392, 256, 208896>>>(img, talng, talnb, taw1, tab1, taw2, tab2);
    k3_cap<<<BT, 256, 208896>>>(cap, lens, calng, calnb, caw1, cab1, casc, fw, fb);
    k4_score<<<BV, 256, 196736>>>(img);
    k5_pair<<<dim3(BT, BV), 512, 199168>>>(img, tasc, out);
}